// round 1
// baseline (speedup 1.0000x reference)
#include <cuda_runtime.h>

// CausalSelfAttention: B=4, T=4096, C=128, fp32.
// Kernel 1: fused QKV projection (writes K transposed [b][c][t], Q pre-scaled).
// Kernel 2: fp32 SIMT flash attention, 64x64 tiles, online softmax.

#define BB 4
#define TT 4096
#define CC 128
#define BT (BB*TT)
#define BQ 64
#define BK 64
#define SCALE 0.08838834764831845f  // 1/sqrt(128)

// Scratch (device globals; no cudaMalloc allowed)
__device__ float g_q[BT*CC];        // [b*T + t][c], pre-scaled by SCALE
__device__ float g_kt[BB*CC*TT];    // [b][c][t]  (transposed K)
__device__ float g_v[BT*CC];        // [b*T + t][c]

// ---------------------------------------------------------------------------
// QKV projection: y[t,d] = sum_c x[t,c] * W[d,c]
// Block: 64 rows x 128 cols for one of {Wq, Wk, Wv}. 256 threads, 4x8 reg tile.
// ---------------------------------------------------------------------------
__global__ __launch_bounds__(256) void qkv_proj(
    const float* __restrict__ x,
    const float* __restrict__ Wq,
    const float* __restrict__ Wk,
    const float* __restrict__ Wv)
{
    const int widx = blockIdx.y;
    const float* __restrict__ W = (widx == 0) ? Wq : ((widx == 1) ? Wk : Wv);
    const int row0 = blockIdx.x * 64;
    const int tid = threadIdx.x;
    const int tx = tid & 15;
    const int ty = tid >> 4;
    const int r0 = ty * 4;      // output rows (4)
    const int c0 = tx * 8;      // output cols (8)

    __shared__ float xs[64 * 32];        // xs[r][k]
    __shared__ float wt[32 * 132];       // wt[k][d], padded row

    float acc[4][8];
#pragma unroll
    for (int i = 0; i < 4; i++)
#pragma unroll
        for (int j = 0; j < 8; j++) acc[i][j] = 0.0f;

    for (int kc = 0; kc < 4; ++kc) {
        __syncthreads();
        // load x tile chunk: 64 x 32 (512 float4)
#pragma unroll
        for (int f = tid; f < 512; f += 256) {
            int r = f >> 3, c4 = f & 7;
            *(float4*)&xs[r * 32 + c4 * 4] =
                *(const float4*)&x[(row0 + r) * CC + kc * 32 + c4 * 4];
        }
        // load W chunk transposed: wt[k][d] = W[d][kc*32+k]  (1024 float4)
#pragma unroll
        for (int f = tid; f < 1024; f += 256) {
            int d = f >> 3, k4 = f & 7;
            float4 w4 = *(const float4*)&W[d * CC + kc * 32 + k4 * 4];
            wt[(k4 * 4 + 0) * 132 + d] = w4.x;
            wt[(k4 * 4 + 1) * 132 + d] = w4.y;
            wt[(k4 * 4 + 2) * 132 + d] = w4.z;
            wt[(k4 * 4 + 3) * 132 + d] = w4.w;
        }
        __syncthreads();

#pragma unroll
        for (int k = 0; k < 32; ++k) {
            float a0 = xs[(r0 + 0) * 32 + k];
            float a1 = xs[(r0 + 1) * 32 + k];
            float a2 = xs[(r0 + 2) * 32 + k];
            float a3 = xs[(r0 + 3) * 32 + k];
            float4 b0 = *(float4*)&wt[k * 132 + c0];
            float4 b1 = *(float4*)&wt[k * 132 + c0 + 4];
            float bf[8] = {b0.x, b0.y, b0.z, b0.w, b1.x, b1.y, b1.z, b1.w};
            float af[4] = {a0, a1, a2, a3};
#pragma unroll
            for (int i = 0; i < 4; i++)
#pragma unroll
                for (int j = 0; j < 8; j++)
                    acc[i][j] += af[i] * bf[j];
        }
    }

    if (widx == 1) {
        // K: store transposed into g_kt[b][c][t]
#pragma unroll
        for (int i = 0; i < 4; i++) {
            int tg = row0 + r0 + i;
            int b = tg >> 12;          // /4096
            int tl = tg & (TT - 1);
            float* base = g_kt + b * CC * TT;
#pragma unroll
            for (int j = 0; j < 8; j++)
                base[(c0 + j) * TT + tl] = acc[i][j];
        }
    } else {
        float* out = (widx == 0) ? g_q : g_v;
        float sc = (widx == 0) ? SCALE : 1.0f;
#pragma unroll
        for (int i = 0; i < 4; i++) {
            float4 s0 = make_float4(acc[i][0] * sc, acc[i][1] * sc,
                                    acc[i][2] * sc, acc[i][3] * sc);
            float4 s1 = make_float4(acc[i][4] * sc, acc[i][5] * sc,
                                    acc[i][6] * sc, acc[i][7] * sc);
            float* op = out + (row0 + r0 + i) * CC + c0;
            *(float4*)&op[0] = s0;
            *(float4*)&op[4] = s1;
        }
    }
}

// ---------------------------------------------------------------------------
// Flash attention, fp32. One block = (batch b, query tile of 64 rows).
// 256 threads as a 16x16 grid: thread owns 4 q-rows x {4 S-cols | 8 O-cols}.
// ---------------------------------------------------------------------------
#define FLASH_SMEM ((BQ*CC + CC*BK + BK*CC + BQ*BK) * 4)  // 114688 B

__global__ __launch_bounds__(256) void flash_attn(float* __restrict__ out)
{
    extern __shared__ float sm[];
    float* qs  = sm;                    // [64][128]
    float* kts = sm + BQ * CC;          // [128][64]   (K^T tile)
    float* vs  = kts + CC * BK;         // [64][128]
    float* ps  = vs + BK * CC;          // [64][64]

    const int qt = (int)gridDim.x - 1 - (int)blockIdx.x;  // big tiles first
    const int b  = blockIdx.y;
    const int tid = threadIdx.x;
    const int tx = tid & 15;
    const int ty = tid >> 4;
    const int r0 = ty * 4;     // q rows owned
    const int cs = tx * 4;     // S cols owned
    const int cv = tx * 8;     // O/V cols owned

    // load Q tile (pre-scaled)
    const float* qg = g_q + (b * TT + qt * BQ) * CC;
#pragma unroll
    for (int f = tid; f < BQ * CC / 4; f += 256)
        *(float4*)&qs[f * 4] = *(const float4*)&qg[f * 4];

    float m[4], l[4], o[4][8];
#pragma unroll
    for (int i = 0; i < 4; i++) {
        m[i] = -1e30f;
        l[i] = 0.0f;
#pragma unroll
        for (int j = 0; j < 8; j++) o[i][j] = 0.0f;
    }

    const float* ktg = g_kt + b * CC * TT;
    const float* vg  = g_v + b * TT * CC;

    for (int j = 0; j <= qt; ++j) {
        __syncthreads();   // previous tile's ps/vs/kts fully consumed
        // load K^T tile: kts[c][r], c in [0,128), r in [0,64)
#pragma unroll
        for (int f = tid; f < CC * BK / 4; f += 256) {
            int c = f >> 4, r4 = f & 15;
            *(float4*)&kts[c * BK + r4 * 4] =
                *(const float4*)&ktg[c * TT + j * BK + r4 * 4];
        }
        // load V tile (row-major, straight copy)
#pragma unroll
        for (int f = tid; f < BK * CC / 4; f += 256)
            *(float4*)&vs[f * 4] = *(const float4*)&vg[j * BK * CC + f * 4];
        __syncthreads();

        // ---- S = Q K^T (4x4 per thread) ----
        float s[4][4];
#pragma unroll
        for (int i = 0; i < 4; i++)
#pragma unroll
            for (int jj = 0; jj < 4; jj++) s[i][jj] = 0.0f;

#pragma unroll
        for (int k = 0; k < CC; k += 4) {
            float4 A[4], Bv[4];
#pragma unroll
            for (int i = 0; i < 4; i++)
                A[i] = *(float4*)&qs[(r0 + i) * CC + k];
#pragma unroll
            for (int kk = 0; kk < 4; kk++)
                Bv[kk] = *(float4*)&kts[(k + kk) * BK + cs];
            const float* Af = (const float*)A;   // Af[i*4+kk]
            const float* Bf = (const float*)Bv;  // Bf[kk*4+jj]
#pragma unroll
            for (int i = 0; i < 4; i++)
#pragma unroll
                for (int jj = 0; jj < 4; jj++)
#pragma unroll
                    for (int kk = 0; kk < 4; kk++)
                        s[i][jj] += Af[i * 4 + kk] * Bf[kk * 4 + jj];
        }

        // ---- causal mask (diagonal tile only) ----
        if (j == qt) {
#pragma unroll
            for (int i = 0; i < 4; i++) {
                int qrow = r0 + i;          // same tile => compare local idx
#pragma unroll
                for (int jj = 0; jj < 4; jj++)
                    if (cs + jj > qrow) s[i][jj] = -1e30f;
            }
        }

        // ---- online softmax (row stats across 16 lanes) ----
#pragma unroll
        for (int i = 0; i < 4; i++) {
            float rm = fmaxf(fmaxf(s[i][0], s[i][1]), fmaxf(s[i][2], s[i][3]));
#pragma unroll
            for (int off = 1; off < 16; off <<= 1)
                rm = fmaxf(rm, __shfl_xor_sync(0xffffffffu, rm, off));
            float mnew = fmaxf(m[i], rm);
            float alpha = __expf(m[i] - mnew);
            float rs = 0.0f;
#pragma unroll
            for (int jj = 0; jj < 4; jj++) {
                float p = __expf(s[i][jj] - mnew);
                s[i][jj] = p;
                rs += p;
            }
#pragma unroll
            for (int off = 1; off < 16; off <<= 1)
                rs += __shfl_xor_sync(0xffffffffu, rs, off);
            l[i] = l[i] * alpha + rs;
            m[i] = mnew;
#pragma unroll
            for (int cc = 0; cc < 8; cc++) o[i][cc] *= alpha;
            *(float4*)&ps[(r0 + i) * BK + cs] =
                make_float4(s[i][0], s[i][1], s[i][2], s[i][3]);
        }
        __syncthreads();   // ps visible to all

        // ---- O += P V  (vectorized over s by 4) ----
#pragma unroll 4
        for (int s4 = 0; s4 < BK; s4 += 4) {
            float4 P[4];
#pragma unroll
            for (int i = 0; i < 4; i++)
                P[i] = *(float4*)&ps[(r0 + i) * BK + s4];
            const float* Pf = (const float*)P;   // Pf[i*4+q]
#pragma unroll
            for (int q = 0; q < 4; q++) {
                float4 v0 = *(float4*)&vs[(s4 + q) * CC + cv];
                float4 v1 = *(float4*)&vs[(s4 + q) * CC + cv + 4];
#pragma unroll
                for (int i = 0; i < 4; i++) {
                    float p = Pf[i * 4 + q];
                    o[i][0] += p * v0.x; o[i][1] += p * v0.y;
                    o[i][2] += p * v0.z; o[i][3] += p * v0.w;
                    o[i][4] += p * v1.x; o[i][5] += p * v1.y;
                    o[i][6] += p * v1.z; o[i][7] += p * v1.w;
                }
            }
        }
    }

    // ---- epilogue ----
#pragma unroll
    for (int i = 0; i < 4; i++) {
        float inv = 1.0f / l[i];
        int t = qt * BQ + r0 + i;
        float* op = out + (b * TT + t) * CC + cv;
        float4 s0 = make_float4(o[i][0] * inv, o[i][1] * inv,
                                o[i][2] * inv, o[i][3] * inv);
        float4 s1 = make_float4(o[i][4] * inv, o[i][5] * inv,
                                o[i][6] * inv, o[i][7] * inv);
        *(float4*)&op[0] = s0;
        *(float4*)&op[4] = s1;
    }
}

// ---------------------------------------------------------------------------
extern "C" void kernel_launch(void* const* d_in, const int* in_sizes, int n_in,
                              void* d_out, int out_size)
{
    const float* x  = (const float*)d_in[0];
    const float* Wq = (const float*)d_in[1];
    const float* Wk = (const float*)d_in[2];
    const float* Wv = (const float*)d_in[3];
    float* out = (float*)d_out;

    cudaFuncSetAttribute(flash_attn,
                         cudaFuncAttributeMaxDynamicSharedMemorySize,
                         FLASH_SMEM);

    qkv_proj<<<dim3(BT / 64, 3), 256>>>(x, Wq, Wk, Wv);
    flash_attn<<<dim3(TT / BQ, BB), 256, FLASH_SMEM>>>(out);
}

// round 2
// speedup vs baseline: 1.0014x; 1.0014x over previous
#include <cuda_runtime.h>

// CausalSelfAttention: B=4, T=4096, C=128, fp32.
// Kernel 1: fused QKV projection (writes K transposed [b][c][t], Q pre-scaled).
// Kernel 2: fp32 SIMT flash attention, 64x64 tiles, online softmax.

#define BB 4
#define TT 4096
#define CC 128
#define BT (BB*TT)
#define BQ 64
#define BK 64
#define SCALE 0.08838834764831845f  // 1/sqrt(128)

// Scratch (device globals; no cudaMalloc allowed)
__device__ float g_q[BT*CC];        // [b*T + t][c], pre-scaled by SCALE
__device__ float g_kt[BB*CC*TT];    // [b][c][t]  (transposed K)
__device__ float g_v[BT*CC];        // [b*T + t][c]

// ---------------------------------------------------------------------------
// QKV projection: y[t,d] = sum_c x[t,c] * W[d,c]
// Block: 64 rows x 128 cols for one of {Wq, Wk, Wv}. 256 threads, 4x8 reg tile.
// ---------------------------------------------------------------------------
__global__ __launch_bounds__(256) void qkv_proj(
    const float* __restrict__ x,
    const float* __restrict__ Wq,
    const float* __restrict__ Wk,
    const float* __restrict__ Wv)
{
    const int widx = blockIdx.y;
    const float* __restrict__ W = (widx == 0) ? Wq : ((widx == 1) ? Wk : Wv);
    const int row0 = blockIdx.x * 64;
    const int tid = threadIdx.x;
    const int tx = tid & 15;
    const int ty = tid >> 4;
    const int r0 = ty * 4;      // output rows (4)
    const int c0 = tx * 8;      // output cols (8)

    __shared__ float xs[64 * 32];        // xs[r][k]
    __shared__ float wt[32 * 132];       // wt[k][d], padded row

    float acc[4][8];
#pragma unroll
    for (int i = 0; i < 4; i++)
#pragma unroll
        for (int j = 0; j < 8; j++) acc[i][j] = 0.0f;

    for (int kc = 0; kc < 4; ++kc) {
        __syncthreads();
        // load x tile chunk: 64 x 32 (512 float4)
#pragma unroll
        for (int f = tid; f < 512; f += 256) {
            int r = f >> 3, c4 = f & 7;
            *(float4*)&xs[r * 32 + c4 * 4] =
                *(const float4*)&x[(row0 + r) * CC + kc * 32 + c4 * 4];
        }
        // load W chunk transposed: wt[k][d] = W[d][kc*32+k]  (1024 float4)
#pragma unroll
        for (int f = tid; f < 1024; f += 256) {
            int d = f >> 3, k4 = f & 7;
            float4 w4 = *(const float4*)&W[d * CC + kc * 32 + k4 * 4];
            wt[(k4 * 4 + 0) * 132 + d] = w4.x;
            wt[(k4 * 4 + 1) * 132 + d] = w4.y;
            wt[(k4 * 4 + 2) * 132 + d] = w4.z;
            wt[(k4 * 4 + 3) * 132 + d] = w4.w;
        }
        __syncthreads();

#pragma unroll
        for (int k = 0; k < 32; ++k) {
            float a0 = xs[(r0 + 0) * 32 + k];
            float a1 = xs[(r0 + 1) * 32 + k];
            float a2 = xs[(r0 + 2) * 32 + k];
            float a3 = xs[(r0 + 3) * 32 + k];
            float4 b0 = *(float4*)&wt[k * 132 + c0];
            float4 b1 = *(float4*)&wt[k * 132 + c0 + 4];
            float bf[8] = {b0.x, b0.y, b0.z, b0.w, b1.x, b1.y, b1.z, b1.w};
            float af[4] = {a0, a1, a2, a3};
#pragma unroll
            for (int i = 0; i < 4; i++)
#pragma unroll
                for (int j = 0; j < 8; j++)
                    acc[i][j] += af[i] * bf[j];
        }
    }

    if (widx == 1) {
        // K: store transposed into g_kt[b][c][t]
#pragma unroll
        for (int i = 0; i < 4; i++) {
            int tg = row0 + r0 + i;
            int b = tg >> 12;          // /4096
            int tl = tg & (TT - 1);
            float* base = g_kt + b * CC * TT;
#pragma unroll
            for (int j = 0; j < 8; j++)
                base[(c0 + j) * TT + tl] = acc[i][j];
        }
    } else {
        float* out = (widx == 0) ? g_q : g_v;
        float sc = (widx == 0) ? SCALE : 1.0f;
#pragma unroll
        for (int i = 0; i < 4; i++) {
            float4 s0 = make_float4(acc[i][0] * sc, acc[i][1] * sc,
                                    acc[i][2] * sc, acc[i][3] * sc);
            float4 s1 = make_float4(acc[i][4] * sc, acc[i][5] * sc,
                                    acc[i][6] * sc, acc[i][7] * sc);
            float* op = out + (row0 + r0 + i) * CC + c0;
            *(float4*)&op[0] = s0;
            *(float4*)&op[4] = s1;
        }
    }
}

// ---------------------------------------------------------------------------
// Flash attention, fp32. One block = (batch b, query tile of 64 rows).
// 256 threads as a 16x16 grid: thread owns 4 q-rows x {4 S-cols | 8 O-cols}.
// ---------------------------------------------------------------------------
#define FLASH_SMEM ((BQ*CC + CC*BK + BK*CC + BQ*BK) * 4)  // 114688 B

__global__ __launch_bounds__(256) void flash_attn(float* __restrict__ out)
{
    extern __shared__ float sm[];
    float* qs  = sm;                    // [64][128]
    float* kts = sm + BQ * CC;          // [128][64]   (K^T tile)
    float* vs  = kts + CC * BK;         // [64][128]
    float* ps  = vs + BK * CC;          // [64][64]

    const int qt = (int)gridDim.x - 1 - (int)blockIdx.x;  // big tiles first
    const int b  = blockIdx.y;
    const int tid = threadIdx.x;
    const int tx = tid & 15;
    const int ty = tid >> 4;
    const int r0 = ty * 4;     // q rows owned
    const int cs = tx * 4;     // S cols owned
    const int cv = tx * 8;     // O/V cols owned

    // load Q tile (pre-scaled)
    const float* qg = g_q + (b * TT + qt * BQ) * CC;
#pragma unroll
    for (int f = tid; f < BQ * CC / 4; f += 256)
        *(float4*)&qs[f * 4] = *(const float4*)&qg[f * 4];

    float m[4], l[4], o[4][8];
#pragma unroll
    for (int i = 0; i < 4; i++) {
        m[i] = -1e30f;
        l[i] = 0.0f;
#pragma unroll
        for (int j = 0; j < 8; j++) o[i][j] = 0.0f;
    }

    const float* ktg = g_kt + b * CC * TT;
    const float* vg  = g_v + b * TT * CC;

    for (int j = 0; j <= qt; ++j) {
        __syncthreads();   // previous tile's ps/vs/kts fully consumed
        // load K^T tile: kts[c][r], c in [0,128), r in [0,64)
#pragma unroll
        for (int f = tid; f < CC * BK / 4; f += 256) {
            int c = f >> 4, r4 = f & 15;
            *(float4*)&kts[c * BK + r4 * 4] =
                *(const float4*)&ktg[c * TT + j * BK + r4 * 4];
        }
        // load V tile (row-major, straight copy)
#pragma unroll
        for (int f = tid; f < BK * CC / 4; f += 256)
            *(float4*)&vs[f * 4] = *(const float4*)&vg[j * BK * CC + f * 4];
        __syncthreads();

        // ---- S = Q K^T (4x4 per thread) ----
        float s[4][4];
#pragma unroll
        for (int i = 0; i < 4; i++)
#pragma unroll
            for (int jj = 0; jj < 4; jj++) s[i][jj] = 0.0f;

#pragma unroll
        for (int k = 0; k < CC; k += 4) {
            float4 A[4], Bv[4];
#pragma unroll
            for (int i = 0; i < 4; i++)
                A[i] = *(float4*)&qs[(r0 + i) * CC + k];
#pragma unroll
            for (int kk = 0; kk < 4; kk++)
                Bv[kk] = *(float4*)&kts[(k + kk) * BK + cs];
            const float* Af = (const float*)A;   // Af[i*4+kk]
            const float* Bf = (const float*)Bv;  // Bf[kk*4+jj]
#pragma unroll
            for (int i = 0; i < 4; i++)
#pragma unroll
                for (int jj = 0; jj < 4; jj++)
#pragma unroll
                    for (int kk = 0; kk < 4; kk++)
                        s[i][jj] += Af[i * 4 + kk] * Bf[kk * 4 + jj];
        }

        // ---- causal mask (diagonal tile only) ----
        if (j == qt) {
#pragma unroll
            for (int i = 0; i < 4; i++) {
                int qrow = r0 + i;          // same tile => compare local idx
#pragma unroll
                for (int jj = 0; jj < 4; jj++)
                    if (cs + jj > qrow) s[i][jj] = -1e30f;
            }
        }

        // ---- online softmax (row stats across 16 lanes) ----
#pragma unroll
        for (int i = 0; i < 4; i++) {
            float rm = fmaxf(fmaxf(s[i][0], s[i][1]), fmaxf(s[i][2], s[i][3]));
#pragma unroll
            for (int off = 1; off < 16; off <<= 1)
                rm = fmaxf(rm, __shfl_xor_sync(0xffffffffu, rm, off));
            float mnew = fmaxf(m[i], rm);
            float alpha = __expf(m[i] - mnew);
            float rs = 0.0f;
#pragma unroll
            for (int jj = 0; jj < 4; jj++) {
                float p = __expf(s[i][jj] - mnew);
                s[i][jj] = p;
                rs += p;
            }
#pragma unroll
            for (int off = 1; off < 16; off <<= 1)
                rs += __shfl_xor_sync(0xffffffffu, rs, off);
            l[i] = l[i] * alpha + rs;
            m[i] = mnew;
#pragma unroll
            for (int cc = 0; cc < 8; cc++) o[i][cc] *= alpha;
            *(float4*)&ps[(r0 + i) * BK + cs] =
                make_float4(s[i][0], s[i][1], s[i][2], s[i][3]);
        }
        __syncthreads();   // ps visible to all

        // ---- O += P V  (vectorized over s by 4) ----
#pragma unroll 4
        for (int s4 = 0; s4 < BK; s4 += 4) {
            float4 P[4];
#pragma unroll
            for (int i = 0; i < 4; i++)
                P[i] = *(float4*)&ps[(r0 + i) * BK + s4];
            const float* Pf = (const float*)P;   // Pf[i*4+q]
#pragma unroll
            for (int q = 0; q < 4; q++) {
                float4 v0 = *(float4*)&vs[(s4 + q) * CC + cv];
                float4 v1 = *(float4*)&vs[(s4 + q) * CC + cv + 4];
#pragma unroll
                for (int i = 0; i < 4; i++) {
                    float p = Pf[i * 4 + q];
                    o[i][0] += p * v0.x; o[i][1] += p * v0.y;
                    o[i][2] += p * v0.z; o[i][3] += p * v0.w;
                    o[i][4] += p * v1.x; o[i][5] += p * v1.y;
                    o[i][6] += p * v1.z; o[i][7] += p * v1.w;
                }
            }
        }
    }

    // ---- epilogue ----
#pragma unroll
    for (int i = 0; i < 4; i++) {
        float inv = 1.0f / l[i];
        int t = qt * BQ + r0 + i;
        float* op = out + (b * TT + t) * CC + cv;
        float4 s0 = make_float4(o[i][0] * inv, o[i][1] * inv,
                                o[i][2] * inv, o[i][3] * inv);
        float4 s1 = make_float4(o[i][4] * inv, o[i][5] * inv,
                                o[i][6] * inv, o[i][7] * inv);
        *(float4*)&op[0] = s0;
        *(float4*)&op[4] = s1;
    }
}

// ---------------------------------------------------------------------------
extern "C" void kernel_launch(void* const* d_in, const int* in_sizes, int n_in,
                              void* d_out, int out_size)
{
    const float* x  = (const float*)d_in[0];
    const float* Wq = (const float*)d_in[1];
    const float* Wk = (const float*)d_in[2];
    const float* Wv = (const float*)d_in[3];
    float* out = (float*)d_out;

    cudaFuncSetAttribute(flash_attn,
                         cudaFuncAttributeMaxDynamicSharedMemorySize,
                         FLASH_SMEM);

    qkv_proj<<<dim3(BT / 64, 3), 256>>>(x, Wq, Wk, Wv);
    flash_attn<<<dim3(TT / BQ, BB), 256, FLASH_SMEM>>>(out);
}